// round 1
// baseline (speedup 1.0000x reference)
#include <cuda_runtime.h>

#define FULL 0xffffffffu

constexpr int N1 = 50000, E1 = 800000, ET1 = E1 + N1;
constexpr int K1 = 1000,  EG = 8000,  ETG = EG + K1;
constexpr int F  = 128,   H  = 4;

// ---------------- scratch (device globals; no allocation allowed) ----------
__device__ __align__(16) float g_h1[N1 * F];     // h = x @ W1
__device__ __align__(16) float g_as1[N1 * H];
__device__ __align__(16) float g_ad1[N1 * H];
__device__ __align__(16) float g_e1[ET1 * H];    // e, then p (in place)
__device__ int   g_m1[N1 * H];
__device__ float g_z1[N1 * H];
__device__ __align__(16) float g_xout[N1 * F];   // x_out accumulator (init = b1)

__device__ __align__(16) float g_hg[K1 * F];
__device__ __align__(16) float g_asg[K1 * H];
__device__ __align__(16) float g_adg[K1 * H];
__device__ __align__(16) float g_eg[ETG * H];
__device__ int   g_mg[K1 * H];
__device__ float g_zg[K1 * H];
__device__ __align__(16) float g_xgout[K1 * F];  // x_g_out accumulator (init = b2)

// ---------------- helpers ---------------------------------------------------
__device__ __forceinline__ int fkey(float f) {
    int i = __float_as_int(f);
    return i >= 0 ? i : (i ^ 0x7fffffff);
}
__device__ __forceinline__ float fdec(int i) {
    return __int_as_float(i >= 0 ? i : (i ^ 0x7fffffff));
}

// ---------------- kernel 1: GEMM + attention dots + acc init ----------------
// warp per row: lane j holds out features {4j..4j+3}; x row broadcast by shfl.
__global__ __launch_bounds__(256) void gemm_att_kernel(
    const float* __restrict__ x, const float* __restrict__ W,
    const float* __restrict__ a_src, const float* __restrict__ a_dst,
    const float* __restrict__ b,
    float* __restrict__ h, float* __restrict__ as_, float* __restrict__ ad_,
    float* __restrict__ acc, int n)
{
    int lane  = threadIdx.x & 31;
    int warp  = (blockIdx.x * blockDim.x + threadIdx.x) >> 5;
    int nwarp = (gridDim.x * blockDim.x) >> 5;
    for (int row = warp; row < n; row += nwarp) {
        const float* xr = x + (size_t)row * F;
        float x0 = xr[lane], x1 = xr[lane + 32], x2 = xr[lane + 64], x3 = xr[lane + 96];
        float4 acc4 = make_float4(0.f, 0.f, 0.f, 0.f);
#pragma unroll
        for (int k = 0; k < F; k++) {
            float xk;
            if      (k < 32) xk = __shfl_sync(FULL, x0, k);
            else if (k < 64) xk = __shfl_sync(FULL, x1, k - 32);
            else if (k < 96) xk = __shfl_sync(FULL, x2, k - 64);
            else             xk = __shfl_sync(FULL, x3, k - 96);
            float4 w = *(const float4*)(W + k * F + 4 * lane);
            acc4.x = fmaf(xk, w.x, acc4.x);
            acc4.y = fmaf(xk, w.y, acc4.y);
            acc4.z = fmaf(xk, w.z, acc4.z);
            acc4.w = fmaf(xk, w.w, acc4.w);
        }
        *(float4*)(h + (size_t)row * F + 4 * lane) = acc4;

        // per-head attention dots; head = lane/8 (f = 4*lane .. 4*lane+3, all one head)
        float4 asv = *(const float4*)(a_src + 4 * lane);
        float4 adv = *(const float4*)(a_dst + 4 * lane);
        float ds = acc4.x * asv.x + acc4.y * asv.y + acc4.z * asv.z + acc4.w * asv.w;
        float dd = acc4.x * adv.x + acc4.y * adv.y + acc4.z * adv.z + acc4.w * adv.w;
#pragma unroll
        for (int o = 4; o; o >>= 1) {
            ds += __shfl_down_sync(FULL, ds, o);
            dd += __shfl_down_sync(FULL, dd, o);
        }
        if ((lane & 7) == 0) {
            as_[row * H + (lane >> 3)] = ds;
            ad_[row * H + (lane >> 3)] = dd;
        }
        // init output accumulator with bias
        float4 bv = *(const float4*)(b + 4 * lane);
        *(float4*)(acc + (size_t)row * F + 4 * lane) = bv;
    }
}

// ---------------- init of segment max / sum ---------------------------------
__global__ void init_mz_kernel() {
    int i = blockIdx.x * blockDim.x + threadIdx.x;
    if (i < N1 * H) { g_m1[i] = (int)0x80000000; g_z1[i] = 0.f; }
    if (i < K1 * H) { g_mg[i] = (int)0x80000000; g_zg[i] = 0.f; }
}

// ---------------- kernel 2: edge scores + segment max -----------------------
__global__ __launch_bounds__(256) void edge_max_kernel(
    const int* __restrict__ src, const int* __restrict__ dst,
    const float* __restrict__ as_, const float* __restrict__ ad_,
    float* __restrict__ e, int* __restrict__ m, int E, int ET)
{
    int t = blockIdx.x * blockDim.x + threadIdx.x;
    if (t >= ET) return;
    int s = t < E ? src[t] : t - E;
    int d = t < E ? dst[t] : t - E;
    float4 av = *(const float4*)(as_ + s * 4);
    float4 dv = *(const float4*)(ad_ + d * 4);
    float v[4] = {av.x + dv.x, av.y + dv.y, av.z + dv.z, av.w + dv.w};
#pragma unroll
    for (int hh = 0; hh < 4; hh++) {
        float vv = v[hh] > 0.f ? v[hh] : 0.2f * v[hh];
        e[(size_t)t * 4 + hh] = vv;
        atomicMax(&m[d * 4 + hh], fkey(vv));
    }
}

// ---------------- kernel 3: exp + segment sum --------------------------------
__global__ __launch_bounds__(256) void edge_exp_kernel(
    const int* __restrict__ dst, float* __restrict__ e,
    const int* __restrict__ m, float* __restrict__ z, int E, int ET)
{
    int t = blockIdx.x * blockDim.x + threadIdx.x;
    if (t >= ET) return;
    int d = t < E ? dst[t] : t - E;
#pragma unroll
    for (int hh = 0; hh < 4; hh++) {
        float p = __expf(e[(size_t)t * 4 + hh] - fdec(m[d * 4 + hh]));
        e[(size_t)t * 4 + hh] = p;
        atomicAdd(&z[d * 4 + hh], p);
    }
}

// ---------------- kernel 4: normalize + scatter aggregate -------------------
// warp per edge; lane j handles f = 4j..4j+3 (head = j/8).
__global__ __launch_bounds__(256) void edge_aggr_kernel(
    const int* __restrict__ src, const int* __restrict__ dst,
    const float* __restrict__ p, const float* __restrict__ z,
    const float* __restrict__ h,
    float* __restrict__ acc, float* __restrict__ alpha_out, int E, int ET)
{
    int lane = threadIdx.x & 31;
    int t = (blockIdx.x * blockDim.x + threadIdx.x) >> 5;
    if (t >= ET) return;
    int s = t < E ? src[t] : t - E;
    int d = t < E ? dst[t] : t - E;
    int hd = lane >> 3;
    float al = p[(size_t)t * 4 + hd] / z[d * 4 + hd];
    if (lane < 4) alpha_out[(size_t)t * 4 + lane] = p[(size_t)t * 4 + lane] / z[d * 4 + lane];
    float4 hv = *(const float4*)(h + (size_t)s * F + 4 * lane);
    float* dp = acc + (size_t)d * F + 4 * lane;
    atomicAdd(dp + 0, al * hv.x);
    atomicAdd(dp + 1, al * hv.y);
    atomicAdd(dp + 2, al * hv.z);
    atomicAdd(dp + 3, al * hv.w);
}

// ---------------- copy x_g_out to output ------------------------------------
__global__ void copy_kernel(const float* __restrict__ s, float* __restrict__ d, int n) {
    int i = blockIdx.x * blockDim.x + threadIdx.x;
    if (i < n) d[i] = s[i];
}

// ---------------- kernel 5: group-attention mixer ---------------------------
// warp per node; 17 candidate rows kept in registers (float4 per lane each).
__global__ __launch_bounds__(256) void mix_kernel(
    const float* __restrict__ xout, const float* __restrict__ xg,
    const int* __restrict__ gidx, const int* __restrict__ nbr,
    float* __restrict__ outf, int n)
{
    int lane = threadIdx.x & 31;
    int w = (blockIdx.x * blockDim.x + threadIdx.x) >> 5;
    if (w >= n) return;
    int gi = gidx[w];
    float4 x4 = *(const float4*)(xout + (size_t)w * F + 4 * lane);

    int rows[17];
    rows[0] = gi;
    const int* nb = nbr + gi * 16;
#pragma unroll
    for (int k = 0; k < 16; k++) rows[k + 1] = nb[k];

    float4 cv[17];
    float s[17];
#pragma unroll
    for (int k = 0; k < 17; k++) {
        cv[k] = *(const float4*)(xg + (size_t)rows[k] * F + 4 * lane);
        float dv = x4.x * cv[k].x + x4.y * cv[k].y + x4.z * cv[k].z + x4.w * cv[k].w;
#pragma unroll
        for (int o = 16; o; o >>= 1) dv += __shfl_xor_sync(FULL, dv, o);
        s[k] = dv;
    }
    float mx = s[0];
#pragma unroll
    for (int k = 1; k < 17; k++) mx = fmaxf(mx, s[k]);
    float sum = 0.f;
#pragma unroll
    for (int k = 0; k < 17; k++) { s[k] = __expf(s[k] - mx); sum += s[k]; }
    float inv = 1.f / sum;
    float4 g4 = make_float4(0.f, 0.f, 0.f, 0.f);
#pragma unroll
    for (int k = 0; k < 17; k++) {
        float wk = s[k] * inv;
        g4.x = fmaf(wk, cv[k].x, g4.x);
        g4.y = fmaf(wk, cv[k].y, g4.y);
        g4.z = fmaf(wk, cv[k].z, g4.z);
        g4.w = fmaf(wk, cv[k].w, g4.w);
    }
    float4 o4;
    o4.x = 0.5f * x4.x + 0.5f * g4.x;
    o4.y = 0.5f * x4.y + 0.5f * g4.y;
    o4.z = 0.5f * x4.z + 0.5f * g4.z;
    o4.w = 0.5f * x4.w + 0.5f * g4.w;
    *(float4*)(outf + (size_t)w * F + 4 * lane) = o4;
}

// ---------------- host ------------------------------------------------------
extern "C" void kernel_launch(void* const* d_in, const int* in_sizes, int n_in,
                              void* d_out, int out_size)
{
    const float* x    = (const float*)d_in[0];
    const int*   ei   = (const int*)  d_in[1];   // [2,E1] : src then dst
    const float* xg   = (const float*)d_in[2];
    const int*   eig  = (const int*)  d_in[3];   // [2,EG]
    const int*   gidx = (const int*)  d_in[4];
    const int*   nbr  = (const int*)  d_in[5];   // [K1,16]
    const float* W1   = (const float*)d_in[6];
    const float* as1  = (const float*)d_in[7];
    const float* ad1  = (const float*)d_in[8];
    const float* b1   = (const float*)d_in[9];
    const float* W2   = (const float*)d_in[10];
    const float* as2  = (const float*)d_in[11];
    const float* ad2  = (const float*)d_in[12];
    const float* b2   = (const float*)d_in[13];

    float* out    = (float*)d_out;
    float* out_xf = out;                       // [N1*F]
    float* out_xg = out_xf + (size_t)N1 * F;   // [K1*F]
    float* out_a1 = out_xg + (size_t)K1 * F;   // [ET1*H]
    float* out_a2 = out_a1 + (size_t)ET1 * H;  // [ETG*H]

    float *p_h1, *p_as1, *p_ad1, *p_e1, *p_z1, *p_xout;
    float *p_hg, *p_asg, *p_adg, *p_eg, *p_zg, *p_xgout;
    int *p_m1, *p_mg;
    cudaGetSymbolAddress((void**)&p_h1,   g_h1);
    cudaGetSymbolAddress((void**)&p_as1,  g_as1);
    cudaGetSymbolAddress((void**)&p_ad1,  g_ad1);
    cudaGetSymbolAddress((void**)&p_e1,   g_e1);
    cudaGetSymbolAddress((void**)&p_m1,   g_m1);
    cudaGetSymbolAddress((void**)&p_z1,   g_z1);
    cudaGetSymbolAddress((void**)&p_xout, g_xout);
    cudaGetSymbolAddress((void**)&p_hg,   g_hg);
    cudaGetSymbolAddress((void**)&p_asg,  g_asg);
    cudaGetSymbolAddress((void**)&p_adg,  g_adg);
    cudaGetSymbolAddress((void**)&p_eg,   g_eg);
    cudaGetSymbolAddress((void**)&p_mg,   g_mg);
    cudaGetSymbolAddress((void**)&p_zg,   g_zg);
    cudaGetSymbolAddress((void**)&p_xgout,g_xgout);

    const int* src1 = ei;
    const int* dst1 = ei + E1;
    const int* srcg = eig;
    const int* dstg = eig + EG;

    // 1) GEMM + attention dots + accumulator init (both graphs)
    gemm_att_kernel<<<(N1 + 7) / 8, 256>>>(x,  W1, as1, ad1, b1, p_h1, p_as1, p_ad1, p_xout,  N1);
    gemm_att_kernel<<<(K1 + 7) / 8, 256>>>(xg, W2, as2, ad2, b2, p_hg, p_asg, p_adg, p_xgout, K1);

    // 2) init segment max / sum
    init_mz_kernel<<<(N1 * H + 255) / 256, 256>>>();

    // 3) edge softmax, main graph
    edge_max_kernel <<<(ET1 + 255) / 256, 256>>>(src1, dst1, p_as1, p_ad1, p_e1, p_m1, E1, ET1);
    edge_exp_kernel <<<(ET1 + 255) / 256, 256>>>(dst1, p_e1, p_m1, p_z1, E1, ET1);
    edge_aggr_kernel<<<(ET1 * 32 + 255) / 256, 256>>>(src1, dst1, p_e1, p_z1, p_h1,
                                                      p_xout, out_a1, E1, ET1);

    // 4) edge softmax, group graph
    edge_max_kernel <<<(ETG + 255) / 256, 256>>>(srcg, dstg, p_asg, p_adg, p_eg, p_mg, EG, ETG);
    edge_exp_kernel <<<(ETG + 255) / 256, 256>>>(dstg, p_eg, p_mg, p_zg, EG, ETG);
    edge_aggr_kernel<<<(ETG * 32 + 255) / 256, 256>>>(srcg, dstg, p_eg, p_zg, p_hg,
                                                      p_xgout, out_a2, EG, ETG);

    // 5) emit x_g_out
    copy_kernel<<<(K1 * F + 255) / 256, 256>>>(p_xgout, out_xg, K1 * F);

    // 6) group-attention mixer -> x_final
    mix_kernel<<<(N1 + 7) / 8, 256>>>(p_xout, p_xgout, gidx, nbr, out_xf, N1);
}

// round 2
// speedup vs baseline: 1.4558x; 1.4558x over previous
#include <cuda_runtime.h>

#define FULL 0xffffffffu
typedef unsigned long long ull;

constexpr int N1 = 50000, E1 = 800000, ET1 = E1 + N1;
constexpr int K1 = 1000,  EG = 8000,  ETG = EG + K1;
constexpr int F  = 128,   H  = 4;

// ---------------- scratch (device globals; no allocation allowed) ----------
__device__ __align__(16) float g_h1[N1 * F];
__device__ __align__(16) float g_as1[N1 * H];
__device__ __align__(16) float g_ad1[N1 * H];
__device__ __align__(16) float g_xout[N1 * F];

__device__ __align__(16) float g_hg[K1 * F];
__device__ __align__(16) float g_asg[K1 * H];
__device__ __align__(16) float g_adg[K1 * H];

// CSR scratch, main graph
__device__ int g_deg1[N1];
__device__ int g_rs1[N1 + 1];
__device__ int g_cur1[N1];
__device__ int g_csrc1[ET1];
__device__ int g_ceid1[ET1];
// CSR scratch, group graph
__device__ int g_degg[K1];
__device__ int g_rsg[K1 + 1];
__device__ int g_curg[K1];
__device__ int g_csrcg[ETG];
__device__ int g_ceidg[ETG];
// nodes-by-group scratch
__device__ int g_gdeg[K1];
__device__ int g_gs[K1 + 1];
__device__ int g_gcur[K1];
__device__ int g_nlist[N1];

// ---------------- f32x2 helpers (Blackwell packed fp32) ---------------------
__device__ __forceinline__ ull pack2(float a, float b) {
    ull r; asm("mov.b64 %0,{%1,%2};" : "=l"(r) : "f"(a), "f"(b)); return r;
}
__device__ __forceinline__ void unpack2(ull v, float& a, float& b) {
    asm("mov.b64 {%0,%1},%2;" : "=f"(a), "=f"(b) : "l"(v));
}
__device__ __forceinline__ ull fma2(ull a, ull b, ull c) {
    ull d; asm("fma.rn.f32x2 %0,%1,%2,%3;" : "=l"(d) : "l"(a), "l"(b), "l"(c)); return d;
}
__device__ __forceinline__ float lrelu(float v) { return v > 0.f ? v : 0.2f * v; }

// ---------------- kernel 1: GEMM + attention dots ---------------------------
// warp handles RPW rows; lane j holds out features {4j..4j+3}.
constexpr int RPW = 4;
__global__ __launch_bounds__(256) void gemm_att_kernel(
    const float* __restrict__ x, const float* __restrict__ W,
    const float* __restrict__ a_src, const float* __restrict__ a_dst,
    float* __restrict__ h, float* __restrict__ as_, float* __restrict__ ad_, int n)
{
    int lane  = threadIdx.x & 31;
    int warp  = (blockIdx.x * blockDim.x + threadIdx.x) >> 5;
    int nwarp = (gridDim.x * blockDim.x) >> 5;
    for (int r0 = warp * RPW; r0 < n; r0 += nwarp * RPW) {
        float xr[RPW][4];
#pragma unroll
        for (int r = 0; r < RPW; r++) {
            int row = min(r0 + r, n - 1);
            const float* xp = x + (size_t)row * F;
            xr[r][0] = xp[lane];      xr[r][1] = xp[lane + 32];
            xr[r][2] = xp[lane + 64]; xr[r][3] = xp[lane + 96];
        }
        ull acc[RPW][2];
#pragma unroll
        for (int r = 0; r < RPW; r++) { acc[r][0] = 0ull; acc[r][1] = 0ull; }

#pragma unroll
        for (int c = 0; c < 4; c++) {
#pragma unroll 8
            for (int k2 = 0; k2 < 32; k2++) {
                int k = c * 32 + k2;
                ulonglong2 wv = *(const ulonglong2*)(W + k * F + 4 * lane);
#pragma unroll
                for (int r = 0; r < RPW; r++) {
                    float xk = __shfl_sync(FULL, xr[r][c], k2);
                    ull xk2 = pack2(xk, xk);
                    acc[r][0] = fma2(xk2, wv.x, acc[r][0]);
                    acc[r][1] = fma2(xk2, wv.y, acc[r][1]);
                }
            }
        }

        float4 asv = *(const float4*)(a_src + 4 * lane);
        float4 adv = *(const float4*)(a_dst + 4 * lane);
#pragma unroll
        for (int r = 0; r < RPW; r++) {
            int row = r0 + r;
            if (row >= n) break;
            float4 o;
            unpack2(acc[r][0], o.x, o.y);
            unpack2(acc[r][1], o.z, o.w);
            *(float4*)(h + (size_t)row * F + 4 * lane) = o;
            float ds = o.x * asv.x + o.y * asv.y + o.z * asv.z + o.w * asv.w;
            float dd = o.x * adv.x + o.y * adv.y + o.z * adv.z + o.w * adv.w;
#pragma unroll
            for (int off = 4; off; off >>= 1) {
                ds += __shfl_down_sync(FULL, ds, off);
                dd += __shfl_down_sync(FULL, dd, off);
            }
            if ((lane & 7) == 0) {
                as_[row * H + (lane >> 3)] = ds;
                ad_[row * H + (lane >> 3)] = dd;
            }
        }
    }
}

// ---------------- CSR build ---------------------------------------------------
__global__ void hist_kernel(const int* __restrict__ dst, int* __restrict__ deg,
                            int E, int ET)
{
    int t = blockIdx.x * blockDim.x + threadIdx.x;
    if (t >= ET) return;
    int d = t < E ? dst[t] : t - E;
    atomicAdd(&deg[d], 1);
}

// single-block exclusive scan; out has n+1 entries
__global__ void scan_kernel(const int* __restrict__ in, int* __restrict__ out, int n)
{
    __shared__ int wsum[32];
    __shared__ int s_carry;
    int tid = threadIdx.x, lane = tid & 31, wid = tid >> 5;
    if (tid == 0) s_carry = 0;
    __syncthreads();
    for (int base = 0; base < n; base += 1024) {
        int i = base + tid;
        int x = (i < n) ? in[i] : 0;
        int v = x;
#pragma unroll
        for (int o = 1; o < 32; o <<= 1) { int t2 = __shfl_up_sync(FULL, v, o); if (lane >= o) v += t2; }
        if (lane == 31) wsum[wid] = v;
        __syncthreads();
        if (wid == 0) {
            int w = wsum[lane];
#pragma unroll
            for (int o = 1; o < 32; o <<= 1) { int t2 = __shfl_up_sync(FULL, w, o); if (lane >= o) w += t2; }
            wsum[lane] = w;
        }
        __syncthreads();
        int incl = v + (wid > 0 ? wsum[wid - 1] : 0);
        int carry = s_carry;
        if (i < n) out[i] = carry + incl - x;
        __syncthreads();
        if (tid == 1023) s_carry = carry + incl;
        __syncthreads();
    }
    if (threadIdx.x == 0) out[n] = s_carry;
}

__global__ void scatter_kernel(const int* __restrict__ src, const int* __restrict__ dst,
                               int* __restrict__ cur, int* __restrict__ csr_src,
                               int* __restrict__ csr_eid, int E, int ET)
{
    int t = blockIdx.x * blockDim.x + threadIdx.x;
    if (t >= ET) return;
    int s = t < E ? src[t] : t - E;
    int d = t < E ? dst[t] : t - E;
    int pos = atomicAdd(&cur[d], 1);
    csr_src[pos] = s;
    csr_eid[pos] = t;
}

__global__ void histn_kernel(const int* __restrict__ gidx, int* __restrict__ gdeg, int n)
{
    int i = blockIdx.x * blockDim.x + threadIdx.x;
    if (i < n) atomicAdd(&gdeg[gidx[i]], 1);
}
__global__ void scattern_kernel(const int* __restrict__ gidx, int* __restrict__ gcur,
                                int* __restrict__ nlist, int n)
{
    int i = blockIdx.x * blockDim.x + threadIdx.x;
    if (i >= n) return;
    int pos = atomicAdd(&gcur[gidx[i]], 1);
    nlist[pos] = i;
}

// ---------------- fused softmax + aggregate (gather, no atomics) ------------
// warp per destination node.
__global__ __launch_bounds__(256) void gat_aggr_kernel(
    const int* __restrict__ csr_src, const int* __restrict__ csr_eid,
    const int* __restrict__ rowstart,
    const float* __restrict__ as_, const float* __restrict__ ad_,
    const float* __restrict__ h, const float* __restrict__ b,
    float* __restrict__ xout, float* __restrict__ alpha_out, int n)
{
    int lane = threadIdx.x & 31;
    int node = (blockIdx.x * blockDim.x + threadIdx.x) >> 5;
    if (node >= n) return;
    int start = rowstart[node], end = rowstart[node + 1];
    int deg = end - start;
    float4 ad4 = *(const float4*)(ad_ + node * 4);

    float4 vc[4];
    float4 m4 = make_float4(-1e30f, -1e30f, -1e30f, -1e30f);
    int cnt = 0;
    for (int idx = lane; idx < deg; idx += 32) {
        int s = csr_src[start + idx];
        float4 a4 = *(const float4*)(as_ + s * 4);
        float4 v;
        v.x = lrelu(a4.x + ad4.x); v.y = lrelu(a4.y + ad4.y);
        v.z = lrelu(a4.z + ad4.z); v.w = lrelu(a4.w + ad4.w);
        if (cnt < 4) vc[cnt] = v;
        m4.x = fmaxf(m4.x, v.x); m4.y = fmaxf(m4.y, v.y);
        m4.z = fmaxf(m4.z, v.z); m4.w = fmaxf(m4.w, v.w);
        cnt++;
    }
#pragma unroll
    for (int o = 16; o; o >>= 1) {
        m4.x = fmaxf(m4.x, __shfl_xor_sync(FULL, m4.x, o));
        m4.y = fmaxf(m4.y, __shfl_xor_sync(FULL, m4.y, o));
        m4.z = fmaxf(m4.z, __shfl_xor_sync(FULL, m4.z, o));
        m4.w = fmaxf(m4.w, __shfl_xor_sync(FULL, m4.w, o));
    }

    float4 z4 = make_float4(0.f, 0.f, 0.f, 0.f);
    cnt = 0;
    for (int idx = lane; idx < deg; idx += 32) {
        float4 v;
        if (cnt < 4) v = vc[cnt];
        else {
            int s = csr_src[start + idx];
            float4 a4 = *(const float4*)(as_ + s * 4);
            v.x = lrelu(a4.x + ad4.x); v.y = lrelu(a4.y + ad4.y);
            v.z = lrelu(a4.z + ad4.z); v.w = lrelu(a4.w + ad4.w);
        }
        float4 p;
        p.x = __expf(v.x - m4.x); p.y = __expf(v.y - m4.y);
        p.z = __expf(v.z - m4.z); p.w = __expf(v.w - m4.w);
        if (cnt < 4) vc[cnt] = p;
        z4.x += p.x; z4.y += p.y; z4.z += p.z; z4.w += p.w;
        cnt++;
    }
#pragma unroll
    for (int o = 16; o; o >>= 1) {
        z4.x += __shfl_xor_sync(FULL, z4.x, o);
        z4.y += __shfl_xor_sync(FULL, z4.y, o);
        z4.z += __shfl_xor_sync(FULL, z4.z, o);
        z4.w += __shfl_xor_sync(FULL, z4.w, o);
    }
    float4 iz = make_float4(1.f / z4.x, 1.f / z4.y, 1.f / z4.z, 1.f / z4.w);

    // alpha writes
    cnt = 0;
    for (int idx = lane; idx < deg; idx += 32) {
        float4 p;
        if (cnt < 4) p = vc[cnt];
        else {
            int s = csr_src[start + idx];
            float4 a4 = *(const float4*)(as_ + s * 4);
            p.x = __expf(lrelu(a4.x + ad4.x) - m4.x);
            p.y = __expf(lrelu(a4.y + ad4.y) - m4.y);
            p.z = __expf(lrelu(a4.z + ad4.z) - m4.z);
            p.w = __expf(lrelu(a4.w + ad4.w) - m4.w);
        }
        int eid = csr_eid[start + idx];
        float4 al = make_float4(p.x * iz.x, p.y * iz.y, p.z * iz.z, p.w * iz.w);
        *(float4*)(alpha_out + (size_t)eid * 4) = al;
        cnt++;
    }

    // aggregate
    int hd = lane >> 3;
    float izh = hd == 0 ? iz.x : (hd == 1 ? iz.y : (hd == 2 ? iz.z : iz.w));
    float4 acc = *(const float4*)(b + 4 * lane);
    for (int e = 0; e < deg; e++) {
        int s = csr_src[start + e];  // broadcast load
        int slot = e >> 5, owner = e & 31;
        float al;
        if (slot < 4) {
            float4 p;
            switch (slot) {
                case 0: p = vc[0]; break;
                case 1: p = vc[1]; break;
                case 2: p = vc[2]; break;
                default: p = vc[3]; break;
            }
            float px = __shfl_sync(FULL, p.x, owner);
            float py = __shfl_sync(FULL, p.y, owner);
            float pz = __shfl_sync(FULL, p.z, owner);
            float pw = __shfl_sync(FULL, p.w, owner);
            al = (hd == 0 ? px : (hd == 1 ? py : (hd == 2 ? pz : pw))) * izh;
        } else {
            // rare fallback (deg > 128): recompute in all lanes (broadcast loads)
            float4 a4 = *(const float4*)(as_ + s * 4);
            float4 p;
            p.x = __expf(lrelu(a4.x + ad4.x) - m4.x);
            p.y = __expf(lrelu(a4.y + ad4.y) - m4.y);
            p.z = __expf(lrelu(a4.z + ad4.z) - m4.z);
            p.w = __expf(lrelu(a4.w + ad4.w) - m4.w);
            al = (hd == 0 ? p.x : (hd == 1 ? p.y : (hd == 2 ? p.z : p.w))) * izh;
        }
        float4 hv = *(const float4*)(h + (size_t)s * F + 4 * lane);
        acc.x = fmaf(al, hv.x, acc.x);
        acc.y = fmaf(al, hv.y, acc.y);
        acc.z = fmaf(al, hv.z, acc.z);
        acc.w = fmaf(al, hv.w, acc.w);
    }
    *(float4*)(xout + (size_t)node * F + 4 * lane) = acc;
}

// ---------------- group-attention mixer (block per group, shared cand) ------
__global__ __launch_bounds__(256) void mix_kernel(
    const float* __restrict__ xout, const float* __restrict__ xg,
    const int* __restrict__ nbr, const int* __restrict__ nlist,
    const int* __restrict__ gstart, float* __restrict__ outf)
{
    __shared__ float srows[17 * 128];
    __shared__ int rowid[17];
    int g = blockIdx.x;
    int tid = threadIdx.x;
    if (tid < 17) rowid[tid] = (tid == 0) ? g : nbr[g * 16 + tid - 1];
    __syncthreads();
    for (int i = tid; i < 17 * 128; i += 256)
        srows[i] = xg[(size_t)rowid[i >> 7] * F + (i & 127)];
    __syncthreads();
    int start = gstart[g], end = gstart[g + 1];
    int lane = tid & 31, w = tid >> 5;
    for (int j = start + w; j < end; j += 8) {
        int node = nlist[j];
        float4 x4 = *(const float4*)(xout + (size_t)node * F + 4 * lane);
        float s[17];
#pragma unroll
        for (int k = 0; k < 17; k++) {
            float4 c = *(const float4*)(srows + k * 128 + 4 * lane);
            float dv = x4.x * c.x + x4.y * c.y + x4.z * c.z + x4.w * c.w;
#pragma unroll
            for (int o = 16; o; o >>= 1) dv += __shfl_xor_sync(FULL, dv, o);
            s[k] = dv;
        }
        float mx = s[0];
#pragma unroll
        for (int k = 1; k < 17; k++) mx = fmaxf(mx, s[k]);
        float sum = 0.f;
#pragma unroll
        for (int k = 0; k < 17; k++) { s[k] = __expf(s[k] - mx); sum += s[k]; }
        float inv = 1.f / sum;
        float4 g4 = make_float4(0.f, 0.f, 0.f, 0.f);
#pragma unroll
        for (int k = 0; k < 17; k++) {
            float wk = s[k] * inv;
            float4 c = *(const float4*)(srows + k * 128 + 4 * lane);
            g4.x = fmaf(wk, c.x, g4.x); g4.y = fmaf(wk, c.y, g4.y);
            g4.z = fmaf(wk, c.z, g4.z); g4.w = fmaf(wk, c.w, g4.w);
        }
        float4 o4 = make_float4(0.5f * (x4.x + g4.x), 0.5f * (x4.y + g4.y),
                                0.5f * (x4.z + g4.z), 0.5f * (x4.w + g4.w));
        *(float4*)(outf + (size_t)node * F + 4 * lane) = o4;
    }
}

// ---------------- host ------------------------------------------------------
extern "C" void kernel_launch(void* const* d_in, const int* in_sizes, int n_in,
                              void* d_out, int out_size)
{
    const float* x    = (const float*)d_in[0];
    const int*   ei   = (const int*)  d_in[1];
    const float* xg   = (const float*)d_in[2];
    const int*   eig  = (const int*)  d_in[3];
    const int*   gidx = (const int*)  d_in[4];
    const int*   nbr  = (const int*)  d_in[5];
    const float* W1   = (const float*)d_in[6];
    const float* as1  = (const float*)d_in[7];
    const float* ad1  = (const float*)d_in[8];
    const float* b1   = (const float*)d_in[9];
    const float* W2   = (const float*)d_in[10];
    const float* as2  = (const float*)d_in[11];
    const float* ad2  = (const float*)d_in[12];
    const float* b2   = (const float*)d_in[13];

    float* out    = (float*)d_out;
    float* out_xf = out;
    float* out_xg = out_xf + (size_t)N1 * F;
    float* out_a1 = out_xg + (size_t)K1 * F;
    float* out_a2 = out_a1 + (size_t)ET1 * H;

    float *p_h1, *p_as1, *p_ad1, *p_xout, *p_hg, *p_asg, *p_adg;
    int *p_deg1, *p_rs1, *p_cur1, *p_csrc1, *p_ceid1;
    int *p_degg, *p_rsg, *p_curg, *p_csrcg, *p_ceidg;
    int *p_gdeg, *p_gs, *p_gcur, *p_nlist;
    cudaGetSymbolAddress((void**)&p_h1,    g_h1);
    cudaGetSymbolAddress((void**)&p_as1,   g_as1);
    cudaGetSymbolAddress((void**)&p_ad1,   g_ad1);
    cudaGetSymbolAddress((void**)&p_xout,  g_xout);
    cudaGetSymbolAddress((void**)&p_hg,    g_hg);
    cudaGetSymbolAddress((void**)&p_asg,   g_asg);
    cudaGetSymbolAddress((void**)&p_adg,   g_adg);
    cudaGetSymbolAddress((void**)&p_deg1,  g_deg1);
    cudaGetSymbolAddress((void**)&p_rs1,   g_rs1);
    cudaGetSymbolAddress((void**)&p_cur1,  g_cur1);
    cudaGetSymbolAddress((void**)&p_csrc1, g_csrc1);
    cudaGetSymbolAddress((void**)&p_ceid1, g_ceid1);
    cudaGetSymbolAddress((void**)&p_degg,  g_degg);
    cudaGetSymbolAddress((void**)&p_rsg,   g_rsg);
    cudaGetSymbolAddress((void**)&p_curg,  g_curg);
    cudaGetSymbolAddress((void**)&p_csrcg, g_csrcg);
    cudaGetSymbolAddress((void**)&p_ceidg, g_ceidg);
    cudaGetSymbolAddress((void**)&p_gdeg,  g_gdeg);
    cudaGetSymbolAddress((void**)&p_gs,    g_gs);
    cudaGetSymbolAddress((void**)&p_gcur,  g_gcur);
    cudaGetSymbolAddress((void**)&p_nlist, g_nlist);

    const int* src1 = ei;
    const int* dst1 = ei + E1;
    const int* srcg = eig;
    const int* dstg = eig + EG;

    // ---- CSR builds (independent of GEMM) ----
    cudaMemsetAsync(p_deg1, 0, N1 * sizeof(int));
    cudaMemsetAsync(p_degg, 0, K1 * sizeof(int));
    cudaMemsetAsync(p_gdeg, 0, K1 * sizeof(int));

    hist_kernel<<<(ET1 + 255) / 256, 256>>>(dst1, p_deg1, E1, ET1);
    scan_kernel<<<1, 1024>>>(p_deg1, p_rs1, N1);
    cudaMemcpyAsync(p_cur1, p_rs1, N1 * sizeof(int), cudaMemcpyDeviceToDevice);
    scatter_kernel<<<(ET1 + 255) / 256, 256>>>(src1, dst1, p_cur1, p_csrc1, p_ceid1, E1, ET1);

    hist_kernel<<<(ETG + 255) / 256, 256>>>(dstg, p_degg, EG, ETG);
    scan_kernel<<<1, 1024>>>(p_degg, p_rsg, K1);
    cudaMemcpyAsync(p_curg, p_rsg, K1 * sizeof(int), cudaMemcpyDeviceToDevice);
    scatter_kernel<<<(ETG + 255) / 256, 256>>>(srcg, dstg, p_curg, p_csrcg, p_ceidg, EG, ETG);

    histn_kernel<<<(N1 + 255) / 256, 256>>>(gidx, p_gdeg, N1);
    scan_kernel<<<1, 1024>>>(p_gdeg, p_gs, K1);
    cudaMemcpyAsync(p_gcur, p_gs, K1 * sizeof(int), cudaMemcpyDeviceToDevice);
    scattern_kernel<<<(N1 + 255) / 256, 256>>>(gidx, p_gcur, p_nlist, N1);

    // ---- GEMM + attention dots ----
    gemm_att_kernel<<<(N1 + RPW * 8 - 1) / (RPW * 8), 256>>>(x,  W1, as1, ad1, p_h1, p_as1, p_ad1, N1);
    gemm_att_kernel<<<(K1 + RPW * 8 - 1) / (RPW * 8), 256>>>(xg, W2, as2, ad2, p_hg, p_asg, p_adg, K1);

    // ---- fused softmax + aggregate ----
    gat_aggr_kernel<<<(N1 * 32 + 255) / 256, 256>>>(p_csrc1, p_ceid1, p_rs1,
        p_as1, p_ad1, p_h1, b1, p_xout, out_a1, N1);
    gat_aggr_kernel<<<(K1 * 32 + 255) / 256, 256>>>(p_csrcg, p_ceidg, p_rsg,
        p_asg, p_adg, p_hg, b2, out_xg, out_a2, K1);

    // ---- group-attention mixer -> x_final ----
    mix_kernel<<<K1, 256>>>(p_xout, out_xg, nbr, p_nlist, p_gs, out_xf);
}

// round 3
// speedup vs baseline: 2.1086x; 1.4485x over previous
#include <cuda_runtime.h>

#define FULL 0xffffffffu
typedef unsigned long long ull;

constexpr int N1 = 50000, E1 = 800000, ET1 = E1 + N1;
constexpr int K1 = 1000,  EG = 8000,  ETG = EG + K1;
constexpr int F  = 128,   H  = 4;
constexpr int NB1 = (N1 + 1023) / 1024;   // 49 scan blocks

// ---------------- scratch (device globals; no allocation allowed) ----------
__device__ __align__(16) float g_h1[N1 * F];
__device__ __align__(16) float g_as1[N1 * H];
__device__ __align__(16) float g_ad1[N1 * H];
__device__ __align__(16) float g_xout[N1 * F];
__device__ __align__(16) float g_p1[ET1 * H];     // scores -> p, CSR order

__device__ __align__(16) float g_hg[K1 * F];
__device__ __align__(16) float g_asg[K1 * H];
__device__ __align__(16) float g_adg[K1 * H];
__device__ __align__(16) float g_pg[ETG * H];

// degree arrays contiguous -> one memset
__device__ int g_deg_all[N1 + 2 * K1];            // deg1 | degg | gdeg
__device__ int g_rs1[N1 + 1];
__device__ int g_cur1[N1];
__device__ int g_bsum[64];
__device__ int g_csrc1[ET1];
__device__ int g_ceid1[ET1];
__device__ int g_rsg[K1 + 1];
__device__ int g_curg[K1];
__device__ int g_csrcg[ETG];
__device__ int g_ceidg[ETG];
__device__ int g_gs[K1 + 1];
__device__ int g_gcur[K1];
__device__ int g_nlist[N1];

// ---------------- f32x2 helpers ---------------------------------------------
__device__ __forceinline__ ull pack2(float a, float b) {
    ull r; asm("mov.b64 %0,{%1,%2};" : "=l"(r) : "f"(a), "f"(b)); return r;
}
__device__ __forceinline__ void unpack2(ull v, float& a, float& b) {
    asm("mov.b64 {%0,%1},%2;" : "=f"(a), "=f"(b) : "l"(v));
}
__device__ __forceinline__ ull fma2(ull a, ull b, ull c) {
    ull d; asm("fma.rn.f32x2 %0,%1,%2,%3;" : "=l"(d) : "l"(a), "l"(b), "l"(c)); return d;
}
__device__ __forceinline__ float lrelu(float v) { return v > 0.f ? v : 0.2f * v; }

// ---------------- kernel: GEMM + attention dots -----------------------------
constexpr int RPW = 4;
__global__ __launch_bounds__(256) void gemm_att_kernel(
    const float* __restrict__ x, const float* __restrict__ W,
    const float* __restrict__ a_src, const float* __restrict__ a_dst,
    float* __restrict__ h, float* __restrict__ as_, float* __restrict__ ad_, int n)
{
    int lane  = threadIdx.x & 31;
    int warp  = (blockIdx.x * blockDim.x + threadIdx.x) >> 5;
    int nwarp = (gridDim.x * blockDim.x) >> 5;
    for (int r0 = warp * RPW; r0 < n; r0 += nwarp * RPW) {
        float xr[RPW][4];
#pragma unroll
        for (int r = 0; r < RPW; r++) {
            int row = min(r0 + r, n - 1);
            const float* xp = x + (size_t)row * F;
            xr[r][0] = xp[lane];      xr[r][1] = xp[lane + 32];
            xr[r][2] = xp[lane + 64]; xr[r][3] = xp[lane + 96];
        }
        ull acc[RPW][2];
#pragma unroll
        for (int r = 0; r < RPW; r++) { acc[r][0] = 0ull; acc[r][1] = 0ull; }
#pragma unroll
        for (int c = 0; c < 4; c++) {
#pragma unroll 8
            for (int k2 = 0; k2 < 32; k2++) {
                int k = c * 32 + k2;
                ulonglong2 wv = *(const ulonglong2*)(W + k * F + 4 * lane);
#pragma unroll
                for (int r = 0; r < RPW; r++) {
                    float xk = __shfl_sync(FULL, xr[r][c], k2);
                    ull xk2 = pack2(xk, xk);
                    acc[r][0] = fma2(xk2, wv.x, acc[r][0]);
                    acc[r][1] = fma2(xk2, wv.y, acc[r][1]);
                }
            }
        }
        float4 asv = *(const float4*)(a_src + 4 * lane);
        float4 adv = *(const float4*)(a_dst + 4 * lane);
#pragma unroll
        for (int r = 0; r < RPW; r++) {
            int row = r0 + r;
            if (row >= n) break;
            float4 o;
            unpack2(acc[r][0], o.x, o.y);
            unpack2(acc[r][1], o.z, o.w);
            *(float4*)(h + (size_t)row * F + 4 * lane) = o;
            float ds = o.x * asv.x + o.y * asv.y + o.z * asv.z + o.w * asv.w;
            float dd = o.x * adv.x + o.y * adv.y + o.z * adv.z + o.w * adv.w;
#pragma unroll
            for (int off = 4; off; off >>= 1) {
                ds += __shfl_down_sync(FULL, ds, off);
                dd += __shfl_down_sync(FULL, dd, off);
            }
            if ((lane & 7) == 0) {
                as_[row * H + (lane >> 3)] = ds;
                ad_[row * H + (lane >> 3)] = dd;
            }
        }
    }
}

// ---------------- CSR build: fused hist / scans / fused scatter -------------
__global__ void hist_all_kernel(const int* __restrict__ dst1, const int* __restrict__ dstg,
                                const int* __restrict__ gidx)
{
    int t = blockIdx.x * blockDim.x + threadIdx.x;
    int* deg1 = g_deg_all;
    int* degg = g_deg_all + N1;
    int* gdeg = g_deg_all + N1 + K1;
    if (t < ET1) { int d = t < E1 ? dst1[t] : t - E1; atomicAdd(&deg1[d], 1); }
    if (t < ETG) { int d = t < EG ? dstg[t] : t - EG; atomicAdd(&degg[d], 1); }
    if (t < N1)  { atomicAdd(&gdeg[gidx[t]], 1); }
}

__global__ __launch_bounds__(1024) void scanA_kernel()
{
    __shared__ int wsum[32];
    const int* deg1 = g_deg_all;
    int tid = threadIdx.x, lane = tid & 31, wid = tid >> 5;
    int i = blockIdx.x * 1024 + tid;
    int x = (i < N1) ? deg1[i] : 0;
    int v = x;
#pragma unroll
    for (int o = 1; o < 32; o <<= 1) { int t2 = __shfl_up_sync(FULL, v, o); if (lane >= o) v += t2; }
    if (lane == 31) wsum[wid] = v;
    __syncthreads();
    if (wid == 0) {
        int w = wsum[lane];
#pragma unroll
        for (int o = 1; o < 32; o <<= 1) { int t2 = __shfl_up_sync(FULL, w, o); if (lane >= o) w += t2; }
        wsum[lane] = w;
    }
    __syncthreads();
    int incl = v + (wid ? wsum[wid - 1] : 0);
    if (i < N1) g_rs1[i] = incl - x;                 // block-local exclusive
    if (tid == 1023) g_bsum[blockIdx.x] = incl;      // block total
}

__global__ __launch_bounds__(1024) void scanB_kernel()
{
    __shared__ int sh[1024];
    int tid = threadIdx.x;
    const int* degg = g_deg_all + N1;
    const int* gdeg = g_deg_all + N1 + K1;

    // 1) exclusive scan of block sums (NB1 <= 64)
    int a0 = (tid < NB1) ? g_bsum[tid] : 0;
    sh[tid] = a0;
    __syncthreads();
    for (int o = 1; o < 64; o <<= 1) {
        int t2 = (tid >= o) ? sh[tid - o] : 0; __syncthreads();
        sh[tid] += t2; __syncthreads();
    }
    if (tid < NB1) g_bsum[tid] = sh[tid] - a0;
    __syncthreads();

    // 2) exclusive scan degg -> rsg, curg
    int a1 = (tid < K1) ? degg[tid] : 0;
    sh[tid] = a1;
    __syncthreads();
    for (int o = 1; o < 1024; o <<= 1) {
        int t2 = (tid >= o) ? sh[tid - o] : 0; __syncthreads();
        sh[tid] += t2; __syncthreads();
    }
    if (tid < K1) { int ex = sh[tid] - a1; g_rsg[tid] = ex; g_curg[tid] = ex; }
    if (tid == 0) g_rsg[K1] = ETG;
    __syncthreads();

    // 3) exclusive scan gdeg -> gs, gcur
    int a2 = (tid < K1) ? gdeg[tid] : 0;
    sh[tid] = a2;
    __syncthreads();
    for (int o = 1; o < 1024; o <<= 1) {
        int t2 = (tid >= o) ? sh[tid - o] : 0; __syncthreads();
        sh[tid] += t2; __syncthreads();
    }
    if (tid < K1) { int ex = sh[tid] - a2; g_gs[tid] = ex; g_gcur[tid] = ex; }
    if (tid == 0) g_gs[K1] = N1;
}

__global__ __launch_bounds__(1024) void scanC_kernel()
{
    int tid = threadIdx.x;
    int i = blockIdx.x * 1024 + tid;
    if (i < N1) {
        int v = g_rs1[i] + g_bsum[blockIdx.x];
        g_rs1[i] = v;
        g_cur1[i] = v;
    }
    if (i == 0) g_rs1[N1] = ET1;
}

__global__ void scatter_all_kernel(const int* __restrict__ src1, const int* __restrict__ dst1,
                                   const int* __restrict__ srcg, const int* __restrict__ dstg,
                                   const int* __restrict__ gidx)
{
    int t = blockIdx.x * blockDim.x + threadIdx.x;
    if (t < ET1) {
        int s = t < E1 ? src1[t] : t - E1;
        int d = t < E1 ? dst1[t] : t - E1;
        int pos = atomicAdd(&g_cur1[d], 1);
        g_csrc1[pos] = s; g_ceid1[pos] = t;
    }
    if (t < ETG) {
        int s = t < EG ? srcg[t] : t - EG;
        int d = t < EG ? dstg[t] : t - EG;
        int pos = atomicAdd(&g_curg[d], 1);
        g_csrcg[pos] = s; g_ceidg[pos] = t;
    }
    if (t < N1) {
        int pos = atomicAdd(&g_gcur[gidx[t]], 1);
        g_nlist[pos] = t;
    }
}

// ---------------- fused softmax + aggregate (gather, no atomics) ------------
__global__ __launch_bounds__(256) void gat_aggr_kernel(
    const int* __restrict__ csr_src, const int* __restrict__ csr_eid,
    const int* __restrict__ rowstart,
    const float* __restrict__ as_, const float* __restrict__ ad_,
    const float* __restrict__ h, const float* __restrict__ b,
    float* __restrict__ p_csr, float* __restrict__ xout,
    float* __restrict__ alpha_out, int n)
{
    int lane = threadIdx.x & 31;
    int node = (blockIdx.x * blockDim.x + threadIdx.x) >> 5;
    if (node >= n) return;
    int start = rowstart[node], end = rowstart[node + 1];
    int deg = end - start;
    float4 ad4 = *(const float4*)(ad_ + node * 4);

    // pass 1: gather a_src, leaky-relu, write scores CSR-ordered, reduce max
    float4 m4 = make_float4(-1e30f, -1e30f, -1e30f, -1e30f);
    for (int idx = lane; idx < deg; idx += 32) {
        int s = csr_src[start + idx];
        float4 a4 = *(const float4*)(as_ + s * 4);
        float4 v;
        v.x = lrelu(a4.x + ad4.x); v.y = lrelu(a4.y + ad4.y);
        v.z = lrelu(a4.z + ad4.z); v.w = lrelu(a4.w + ad4.w);
        *(float4*)(p_csr + (size_t)(start + idx) * 4) = v;
        m4.x = fmaxf(m4.x, v.x); m4.y = fmaxf(m4.y, v.y);
        m4.z = fmaxf(m4.z, v.z); m4.w = fmaxf(m4.w, v.w);
    }
#pragma unroll
    for (int o = 16; o; o >>= 1) {
        m4.x = fmaxf(m4.x, __shfl_xor_sync(FULL, m4.x, o));
        m4.y = fmaxf(m4.y, __shfl_xor_sync(FULL, m4.y, o));
        m4.z = fmaxf(m4.z, __shfl_xor_sync(FULL, m4.z, o));
        m4.w = fmaxf(m4.w, __shfl_xor_sync(FULL, m4.w, o));
    }

    // pass 2: exp in place (coalesced), reduce z
    float4 z4 = make_float4(0.f, 0.f, 0.f, 0.f);
    for (int idx = lane; idx < deg; idx += 32) {
        float4 v = *(const float4*)(p_csr + (size_t)(start + idx) * 4);
        float4 p;
        p.x = __expf(v.x - m4.x); p.y = __expf(v.y - m4.y);
        p.z = __expf(v.z - m4.z); p.w = __expf(v.w - m4.w);
        *(float4*)(p_csr + (size_t)(start + idx) * 4) = p;
        z4.x += p.x; z4.y += p.y; z4.z += p.z; z4.w += p.w;
    }
#pragma unroll
    for (int o = 16; o; o >>= 1) {
        z4.x += __shfl_xor_sync(FULL, z4.x, o);
        z4.y += __shfl_xor_sync(FULL, z4.y, o);
        z4.z += __shfl_xor_sync(FULL, z4.z, o);
        z4.w += __shfl_xor_sync(FULL, z4.w, o);
    }
    float4 iz = make_float4(1.f / z4.x, 1.f / z4.y, 1.f / z4.z, 1.f / z4.w);

    // pass 3: alpha writes (coalesced read, scattered 16B write)
    for (int idx = lane; idx < deg; idx += 32) {
        float4 p = *(const float4*)(p_csr + (size_t)(start + idx) * 4);
        int eid = csr_eid[start + idx];
        float4 al = make_float4(p.x * iz.x, p.y * iz.y, p.z * iz.z, p.w * iz.w);
        *(float4*)(alpha_out + (size_t)eid * 4) = al;
    }

    // pass 4: aggregate (broadcast p + coalesced h row per edge)
    int hd = lane >> 3;
    float izh = hd == 0 ? iz.x : (hd == 1 ? iz.y : (hd == 2 ? iz.z : iz.w));
    float4 acc = *(const float4*)(b + 4 * lane);
    for (int e = 0; e < deg; e++) {
        int s = csr_src[start + e];                         // broadcast
        float4 p4 = *(const float4*)(p_csr + (size_t)(start + e) * 4);  // broadcast
        float al = (hd == 0 ? p4.x : (hd == 1 ? p4.y : (hd == 2 ? p4.z : p4.w))) * izh;
        float4 hv = *(const float4*)(h + (size_t)s * F + 4 * lane);
        acc.x = fmaf(al, hv.x, acc.x);
        acc.y = fmaf(al, hv.y, acc.y);
        acc.z = fmaf(al, hv.z, acc.z);
        acc.w = fmaf(al, hv.w, acc.w);
    }
    *(float4*)(xout + (size_t)node * F + 4 * lane) = acc;
}

// ---------------- group-attention mixer -------------------------------------
__global__ __launch_bounds__(256) void mix_kernel(
    const float* __restrict__ xout, const float* __restrict__ xg,
    const int* __restrict__ nbr, const int* __restrict__ nlist,
    const int* __restrict__ gstart, float* __restrict__ outf)
{
    __shared__ float srows[17 * 128];
    __shared__ int rowid[17];
    int g = blockIdx.x;
    int tid = threadIdx.x;
    if (tid < 17) rowid[tid] = (tid == 0) ? g : nbr[g * 16 + tid - 1];
    __syncthreads();
    for (int i = tid; i < 17 * 128; i += 256)
        srows[i] = xg[(size_t)rowid[i >> 7] * F + (i & 127)];
    __syncthreads();
    int start = gstart[g], end = gstart[g + 1];
    int lane = tid & 31, w = tid >> 5;
    for (int j = start + w; j < end; j += 8) {
        int node = nlist[j];
        float4 x4 = *(const float4*)(xout + (size_t)node * F + 4 * lane);
        float s[17];
#pragma unroll
        for (int k = 0; k < 17; k++) {
            float4 c = *(const float4*)(srows + k * 128 + 4 * lane);
            float dv = x4.x * c.x + x4.y * c.y + x4.z * c.z + x4.w * c.w;
#pragma unroll
            for (int o = 16; o; o >>= 1) dv += __shfl_xor_sync(FULL, dv, o);
            s[k] = dv;
        }
        float mx = s[0];
#pragma unroll
        for (int k = 1; k < 17; k++) mx = fmaxf(mx, s[k]);
        float sum = 0.f;
#pragma unroll
        for (int k = 0; k < 17; k++) { s[k] = __expf(s[k] - mx); sum += s[k]; }
        float inv = 1.f / sum;
        float4 g4 = make_float4(0.f, 0.f, 0.f, 0.f);
#pragma unroll
        for (int k = 0; k < 17; k++) {
            float wk = s[k] * inv;
            float4 c = *(const float4*)(srows + k * 128 + 4 * lane);
            g4.x = fmaf(wk, c.x, g4.x); g4.y = fmaf(wk, c.y, g4.y);
            g4.z = fmaf(wk, c.z, g4.z); g4.w = fmaf(wk, c.w, g4.w);
        }
        float4 o4 = make_float4(0.5f * (x4.x + g4.x), 0.5f * (x4.y + g4.y),
                                0.5f * (x4.z + g4.z), 0.5f * (x4.w + g4.w));
        *(float4*)(outf + (size_t)node * F + 4 * lane) = o4;
    }
}

// ---------------- streams/events (created at static init, pre-checkpoint) ---
namespace {
struct SideStream {
    cudaStream_t s1 = nullptr;
    cudaEvent_t evFork = nullptr, evS1 = nullptr;
    bool ok = false;
    SideStream() {
        ok = (cudaStreamCreateWithFlags(&s1, cudaStreamNonBlocking) == cudaSuccess) &&
             (cudaEventCreateWithFlags(&evFork, cudaEventDisableTiming) == cudaSuccess) &&
             (cudaEventCreateWithFlags(&evS1, cudaEventDisableTiming) == cudaSuccess);
    }
};
SideStream g_ss;
}

// ---------------- host ------------------------------------------------------
extern "C" void kernel_launch(void* const* d_in, const int* in_sizes, int n_in,
                              void* d_out, int out_size)
{
    const float* x    = (const float*)d_in[0];
    const int*   ei   = (const int*)  d_in[1];
    const float* xg   = (const float*)d_in[2];
    const int*   eig  = (const int*)  d_in[3];
    const int*   gidx = (const int*)  d_in[4];
    const int*   nbr  = (const int*)  d_in[5];
    const float* W1   = (const float*)d_in[6];
    const float* as1  = (const float*)d_in[7];
    const float* ad1  = (const float*)d_in[8];
    const float* b1   = (const float*)d_in[9];
    const float* W2   = (const float*)d_in[10];
    const float* as2  = (const float*)d_in[11];
    const float* ad2  = (const float*)d_in[12];
    const float* b2   = (const float*)d_in[13];

    float* out    = (float*)d_out;
    float* out_xf = out;
    float* out_xg = out_xf + (size_t)N1 * F;
    float* out_a1 = out_xg + (size_t)K1 * F;
    float* out_a2 = out_a1 + (size_t)ET1 * H;

    float *p_h1, *p_as1, *p_ad1, *p_xout, *p_p1;
    float *p_hg, *p_asg, *p_adg, *p_pg;
    int *p_deg_all, *p_rs1, *p_csrc1, *p_ceid1;
    int *p_rsg, *p_csrcg, *p_ceidg, *p_gs, *p_nlist;
    cudaGetSymbolAddress((void**)&p_h1,     g_h1);
    cudaGetSymbolAddress((void**)&p_as1,    g_as1);
    cudaGetSymbolAddress((void**)&p_ad1,    g_ad1);
    cudaGetSymbolAddress((void**)&p_xout,   g_xout);
    cudaGetSymbolAddress((void**)&p_p1,     g_p1);
    cudaGetSymbolAddress((void**)&p_hg,     g_hg);
    cudaGetSymbolAddress((void**)&p_asg,    g_asg);
    cudaGetSymbolAddress((void**)&p_adg,    g_adg);
    cudaGetSymbolAddress((void**)&p_pg,     g_pg);
    cudaGetSymbolAddress((void**)&p_deg_all,g_deg_all);
    cudaGetSymbolAddress((void**)&p_rs1,    g_rs1);
    cudaGetSymbolAddress((void**)&p_csrc1,  g_csrc1);
    cudaGetSymbolAddress((void**)&p_ceid1,  g_ceid1);
    cudaGetSymbolAddress((void**)&p_rsg,    g_rsg);
    cudaGetSymbolAddress((void**)&p_csrcg,  g_csrcg);
    cudaGetSymbolAddress((void**)&p_ceidg,  g_ceidg);
    cudaGetSymbolAddress((void**)&p_gs,     g_gs);
    cudaGetSymbolAddress((void**)&p_nlist,  g_nlist);

    const int* src1 = ei;
    const int* dst1 = ei + E1;
    const int* srcg = eig;
    const int* dstg = eig + EG;

    bool fork = g_ss.ok;
    cudaStream_t s1 = fork ? g_ss.s1 : (cudaStream_t)0;

    if (fork) {
        cudaEventRecord(g_ss.evFork, 0);
        cudaStreamWaitEvent(s1, g_ss.evFork, 0);
    }

    // ---- side branch: CSR builds + group-graph pipeline ----
    cudaMemsetAsync(p_deg_all, 0, (N1 + 2 * K1) * sizeof(int), s1);
    hist_all_kernel<<<(ET1 + 255) / 256, 256, 0, s1>>>(dst1, dstg, gidx);
    scanA_kernel<<<NB1, 1024, 0, s1>>>();
    scanB_kernel<<<1, 1024, 0, s1>>>();
    scanC_kernel<<<NB1, 1024, 0, s1>>>();
    scatter_all_kernel<<<(ET1 + 255) / 256, 256, 0, s1>>>(src1, dst1, srcg, dstg, gidx);
    gemm_att_kernel<<<(K1 + RPW * 8 - 1) / (RPW * 8), 256, 0, s1>>>(
        xg, W2, as2, ad2, p_hg, p_asg, p_adg, K1);
    gat_aggr_kernel<<<(K1 * 32 + 255) / 256, 256, 0, s1>>>(
        p_csrcg, p_ceidg, p_rsg, p_asg, p_adg, p_hg, b2, p_pg, out_xg, out_a2, K1);
    if (fork) cudaEventRecord(g_ss.evS1, s1);

    // ---- main branch: big GEMM (overlaps side branch) ----
    gemm_att_kernel<<<(N1 + RPW * 8 - 1) / (RPW * 8), 256>>>(
        x, W1, as1, ad1, p_h1, p_as1, p_ad1, N1);

    if (fork) cudaStreamWaitEvent(0, g_ss.evS1, 0);

    // ---- main softmax + aggregate ----
    gat_aggr_kernel<<<(N1 * 32 + 255) / 256, 256>>>(
        p_csrc1, p_ceid1, p_rs1, p_as1, p_ad1, p_h1, b1, p_p1, p_xout, out_a1, N1);

    // ---- group-attention mixer -> x_final ----
    mix_kernel<<<K1, 256>>>(p_xout, out_xg, nbr, p_nlist, p_gs, out_xf);
}

// round 4
// speedup vs baseline: 2.4452x; 1.1596x over previous
#include <cuda_runtime.h>

#define FULL 0xffffffffu
typedef unsigned long long ull;

constexpr int N1 = 50000, E1 = 800000, ET1 = E1 + N1;
constexpr int K1 = 1000,  EG = 8000,  ETG = EG + K1;
constexpr int F  = 128,   H  = 4;
constexpr int NB1 = (N1 + 1023) / 1024;   // 49 scan blocks

// ---------------- scratch (device globals; no allocation allowed) ----------
__device__ __align__(16) float g_h1[N1 * F];
__device__ __align__(16) float g_as1[N1 * H];
__device__ __align__(16) float g_ad1[N1 * H];
__device__ __align__(16) float g_xout[N1 * F];
__device__ __align__(16) float g_p1[ET1 * H];

__device__ __align__(16) float g_hg[K1 * F];
__device__ __align__(16) float g_asg[K1 * H];
__device__ __align__(16) float g_adg[K1 * H];
__device__ __align__(16) float g_pg[ETG * H];

__device__ int g_deg_all[N1 + 2 * K1];            // deg1 | degg | gdeg
__device__ int g_rs1[N1 + 1];
__device__ int g_cur1[N1];
__device__ int g_bsum[64];
__device__ int g_csrc1[ET1];
__device__ int g_ceid1[ET1];
__device__ int g_rsg[K1 + 1];
__device__ int g_curg[K1];
__device__ int g_csrcg[ETG];
__device__ int g_ceidg[ETG];
__device__ int g_gs[K1 + 1];
__device__ int g_gcur[K1];
__device__ int g_nlist[N1];

// ---------------- f32x2 helpers ---------------------------------------------
__device__ __forceinline__ ull pack2(float a, float b) {
    ull r; asm("mov.b64 %0,{%1,%2};" : "=l"(r) : "f"(a), "f"(b)); return r;
}
__device__ __forceinline__ void unpack2(ull v, float& a, float& b) {
    asm("mov.b64 {%0,%1},%2;" : "=f"(a), "=f"(b) : "l"(v));
}
__device__ __forceinline__ ull fma2(ull a, ull b, ull c) {
    ull d; asm("fma.rn.f32x2 %0,%1,%2,%3;" : "=l"(d) : "l"(a), "l"(b), "l"(c)); return d;
}
__device__ __forceinline__ float lrelu(float v) { return v > 0.f ? v : 0.2f * v; }

// ---------------- kernel: GEMM + attention dots -----------------------------
constexpr int RPW = 8;
__global__ __launch_bounds__(256) void gemm_att_kernel(
    const float* __restrict__ x, const float* __restrict__ W,
    const float* __restrict__ a_src, const float* __restrict__ a_dst,
    float* __restrict__ h, float* __restrict__ as_, float* __restrict__ ad_, int n)
{
    int lane  = threadIdx.x & 31;
    int warp  = (blockIdx.x * blockDim.x + threadIdx.x) >> 5;
    int nwarp = (gridDim.x * blockDim.x) >> 5;
    for (int r0 = warp * RPW; r0 < n; r0 += nwarp * RPW) {
        float xr[RPW][4];
#pragma unroll
        for (int r = 0; r < RPW; r++) {
            int row = min(r0 + r, n - 1);
            const float* xp = x + (size_t)row * F;
            xr[r][0] = xp[lane];      xr[r][1] = xp[lane + 32];
            xr[r][2] = xp[lane + 64]; xr[r][3] = xp[lane + 96];
        }
        ull acc[RPW][2];
#pragma unroll
        for (int r = 0; r < RPW; r++) { acc[r][0] = 0ull; acc[r][1] = 0ull; }
#pragma unroll
        for (int c = 0; c < 4; c++) {
#pragma unroll 4
            for (int k2 = 0; k2 < 32; k2++) {
                int k = c * 32 + k2;
                ulonglong2 wv = *(const ulonglong2*)(W + k * F + 4 * lane);
#pragma unroll
                for (int r = 0; r < RPW; r++) {
                    float xk = __shfl_sync(FULL, xr[r][c], k2);
                    ull xk2 = pack2(xk, xk);
                    acc[r][0] = fma2(xk2, wv.x, acc[r][0]);
                    acc[r][1] = fma2(xk2, wv.y, acc[r][1]);
                }
            }
        }
        float4 asv = *(const float4*)(a_src + 4 * lane);
        float4 adv = *(const float4*)(a_dst + 4 * lane);
#pragma unroll
        for (int r = 0; r < RPW; r++) {
            int row = r0 + r;
            if (row >= n) break;
            float4 o;
            unpack2(acc[r][0], o.x, o.y);
            unpack2(acc[r][1], o.z, o.w);
            *(float4*)(h + (size_t)row * F + 4 * lane) = o;
            float ds = o.x * asv.x + o.y * asv.y + o.z * asv.z + o.w * asv.w;
            float dd = o.x * adv.x + o.y * adv.y + o.z * adv.z + o.w * adv.w;
#pragma unroll
            for (int off = 4; off; off >>= 1) {
                ds += __shfl_down_sync(FULL, ds, off);
                dd += __shfl_down_sync(FULL, dd, off);
            }
            if ((lane & 7) == 0) {
                as_[row * H + (lane >> 3)] = ds;
                ad_[row * H + (lane >> 3)] = dd;
            }
        }
    }
}

// ---------------- CSR build --------------------------------------------------
__global__ void hist_all_kernel(const int* __restrict__ dst1, const int* __restrict__ dstg,
                                const int* __restrict__ gidx)
{
    int t = blockIdx.x * blockDim.x + threadIdx.x;
    int* deg1 = g_deg_all;
    int* degg = g_deg_all + N1;
    int* gdeg = g_deg_all + N1 + K1;
    if (t < ET1) { int d = t < E1 ? dst1[t] : t - E1; atomicAdd(&deg1[d], 1); }
    if (t < ETG) { int d = t < EG ? dstg[t] : t - EG; atomicAdd(&degg[d], 1); }
    if (t < N1)  { atomicAdd(&gdeg[gidx[t]], 1); }
}

__global__ __launch_bounds__(1024) void scanA_kernel()
{
    __shared__ int wsum[32];
    const int* deg1 = g_deg_all;
    int tid = threadIdx.x, lane = tid & 31, wid = tid >> 5;
    int i = blockIdx.x * 1024 + tid;
    int x = (i < N1) ? deg1[i] : 0;
    int v = x;
#pragma unroll
    for (int o = 1; o < 32; o <<= 1) { int t2 = __shfl_up_sync(FULL, v, o); if (lane >= o) v += t2; }
    if (lane == 31) wsum[wid] = v;
    __syncthreads();
    if (wid == 0) {
        int w = wsum[lane];
#pragma unroll
        for (int o = 1; o < 32; o <<= 1) { int t2 = __shfl_up_sync(FULL, w, o); if (lane >= o) w += t2; }
        wsum[lane] = w;
    }
    __syncthreads();
    int incl = v + (wid ? wsum[wid - 1] : 0);
    if (i < N1) g_rs1[i] = incl - x;
    if (tid == 1023) g_bsum[blockIdx.x] = incl;
}

__global__ __launch_bounds__(1024) void scanB_kernel()
{
    __shared__ int sh[1024];
    int tid = threadIdx.x;
    const int* degg = g_deg_all + N1;
    const int* gdeg = g_deg_all + N1 + K1;

    int a0 = (tid < NB1) ? g_bsum[tid] : 0;
    sh[tid] = a0;
    __syncthreads();
    for (int o = 1; o < 64; o <<= 1) {
        int t2 = (tid >= o) ? sh[tid - o] : 0; __syncthreads();
        sh[tid] += t2; __syncthreads();
    }
    if (tid < NB1) g_bsum[tid] = sh[tid] - a0;
    __syncthreads();

    int a1 = (tid < K1) ? degg[tid] : 0;
    sh[tid] = a1;
    __syncthreads();
    for (int o = 1; o < 1024; o <<= 1) {
        int t2 = (tid >= o) ? sh[tid - o] : 0; __syncthreads();
        sh[tid] += t2; __syncthreads();
    }
    if (tid < K1) { int ex = sh[tid] - a1; g_rsg[tid] = ex; g_curg[tid] = ex; }
    if (tid == 0) g_rsg[K1] = ETG;
    __syncthreads();

    int a2 = (tid < K1) ? gdeg[tid] : 0;
    sh[tid] = a2;
    __syncthreads();
    for (int o = 1; o < 1024; o <<= 1) {
        int t2 = (tid >= o) ? sh[tid - o] : 0; __syncthreads();
        sh[tid] += t2; __syncthreads();
    }
    if (tid < K1) { int ex = sh[tid] - a2; g_gs[tid] = ex; g_gcur[tid] = ex; }
    if (tid == 0) g_gs[K1] = N1;
}

__global__ __launch_bounds__(1024) void scanC_kernel()
{
    int tid = threadIdx.x;
    int i = blockIdx.x * 1024 + tid;
    if (i < N1) {
        int v = g_rs1[i] + g_bsum[blockIdx.x];
        g_rs1[i] = v;
        g_cur1[i] = v;
    }
    if (i == 0) g_rs1[N1] = ET1;
}

__global__ void scatter_all_kernel(const int* __restrict__ src1, const int* __restrict__ dst1,
                                   const int* __restrict__ srcg, const int* __restrict__ dstg,
                                   const int* __restrict__ gidx)
{
    int t = blockIdx.x * blockDim.x + threadIdx.x;
    if (t < ET1) {
        int s = t < E1 ? src1[t] : t - E1;
        int d = t < E1 ? dst1[t] : t - E1;
        int pos = atomicAdd(&g_cur1[d], 1);
        g_csrc1[pos] = s; g_ceid1[pos] = t;
    }
    if (t < ETG) {
        int s = t < EG ? srcg[t] : t - EG;
        int d = t < EG ? dstg[t] : t - EG;
        int pos = atomicAdd(&g_curg[d], 1);
        g_csrcg[pos] = s; g_ceidg[pos] = t;
    }
    if (t < N1) {
        int pos = atomicAdd(&g_gcur[gidx[t]], 1);
        g_nlist[pos] = t;
    }
}

// ---------------- fused softmax + aggregate (no max pass, no atomics) -------
__global__ __launch_bounds__(256) void gat_aggr_kernel(
    const int* __restrict__ csr_src, const int* __restrict__ csr_eid,
    const int* __restrict__ rowstart,
    const float* __restrict__ as_, const float* __restrict__ ad_,
    const float* __restrict__ h, const float* __restrict__ b,
    float* __restrict__ p_csr, float* __restrict__ xout,
    float* __restrict__ alpha_out, int n)
{
    int lane = threadIdx.x & 31;
    int node = (blockIdx.x * blockDim.x + threadIdx.x) >> 5;
    if (node >= n) return;
    int start = rowstart[node], end = rowstart[node + 1];
    int deg = end - start;
    float4 ad4 = *(const float4*)(ad_ + node * 4);

    // pass A: gather a_src, score, exp (no max shift needed: |e| <~ 10), sum z
    float4 z4 = make_float4(0.f, 0.f, 0.f, 0.f);
    for (int idx = lane; idx < deg; idx += 32) {
        int s = csr_src[start + idx];
        float4 a4 = *(const float4*)(as_ + s * 4);
        float4 p;
        p.x = __expf(lrelu(a4.x + ad4.x));
        p.y = __expf(lrelu(a4.y + ad4.y));
        p.z = __expf(lrelu(a4.z + ad4.z));
        p.w = __expf(lrelu(a4.w + ad4.w));
        *(float4*)(p_csr + (size_t)(start + idx) * 4) = p;
        z4.x += p.x; z4.y += p.y; z4.z += p.z; z4.w += p.w;
    }
#pragma unroll
    for (int o = 16; o; o >>= 1) {
        z4.x += __shfl_xor_sync(FULL, z4.x, o);
        z4.y += __shfl_xor_sync(FULL, z4.y, o);
        z4.z += __shfl_xor_sync(FULL, z4.z, o);
        z4.w += __shfl_xor_sync(FULL, z4.w, o);
    }
    float4 iz = make_float4(1.f / z4.x, 1.f / z4.y, 1.f / z4.z, 1.f / z4.w);

    // pass B: alpha writes (coalesced read, scattered 16B write)
    for (int idx = lane; idx < deg; idx += 32) {
        float4 p = *(const float4*)(p_csr + (size_t)(start + idx) * 4);
        int eid = csr_eid[start + idx];
        float4 al = make_float4(p.x * iz.x, p.y * iz.y, p.z * iz.z, p.w * iz.w);
        *(float4*)(alpha_out + (size_t)eid * 4) = al;
    }

    // pass C: aggregate, unrolled x4 for h-gather MLP
    int hd = lane >> 3;
    float izh = hd == 0 ? iz.x : (hd == 1 ? iz.y : (hd == 2 ? iz.z : iz.w));
    float4 acc = *(const float4*)(b + 4 * lane);
    int e = 0;
    for (; e + 4 <= deg; e += 4) {
        int s0 = csr_src[start + e + 0];
        int s1 = csr_src[start + e + 1];
        int s2 = csr_src[start + e + 2];
        int s3 = csr_src[start + e + 3];
        float4 q0 = *(const float4*)(p_csr + (size_t)(start + e + 0) * 4);
        float4 q1 = *(const float4*)(p_csr + (size_t)(start + e + 1) * 4);
        float4 q2 = *(const float4*)(p_csr + (size_t)(start + e + 2) * 4);
        float4 q3 = *(const float4*)(p_csr + (size_t)(start + e + 3) * 4);
        float4 h0 = *(const float4*)(h + (size_t)s0 * F + 4 * lane);
        float4 h1 = *(const float4*)(h + (size_t)s1 * F + 4 * lane);
        float4 h2 = *(const float4*)(h + (size_t)s2 * F + 4 * lane);
        float4 h3 = *(const float4*)(h + (size_t)s3 * F + 4 * lane);
        float a0 = (hd == 0 ? q0.x : (hd == 1 ? q0.y : (hd == 2 ? q0.z : q0.w))) * izh;
        float a1 = (hd == 0 ? q1.x : (hd == 1 ? q1.y : (hd == 2 ? q1.z : q1.w))) * izh;
        float a2 = (hd == 0 ? q2.x : (hd == 1 ? q2.y : (hd == 2 ? q2.z : q2.w))) * izh;
        float a3 = (hd == 0 ? q3.x : (hd == 1 ? q3.y : (hd == 2 ? q3.z : q3.w))) * izh;
        acc.x = fmaf(a0, h0.x, acc.x); acc.y = fmaf(a0, h0.y, acc.y);
        acc.z = fmaf(a0, h0.z, acc.z); acc.w = fmaf(a0, h0.w, acc.w);
        acc.x = fmaf(a1, h1.x, acc.x); acc.y = fmaf(a1, h1.y, acc.y);
        acc.z = fmaf(a1, h1.z, acc.z); acc.w = fmaf(a1, h1.w, acc.w);
        acc.x = fmaf(a2, h2.x, acc.x); acc.y = fmaf(a2, h2.y, acc.y);
        acc.z = fmaf(a2, h2.z, acc.z); acc.w = fmaf(a2, h2.w, acc.w);
        acc.x = fmaf(a3, h3.x, acc.x); acc.y = fmaf(a3, h3.y, acc.y);
        acc.z = fmaf(a3, h3.z, acc.z); acc.w = fmaf(a3, h3.w, acc.w);
    }
    for (; e < deg; e++) {
        int s = csr_src[start + e];
        float4 q = *(const float4*)(p_csr + (size_t)(start + e) * 4);
        float al = (hd == 0 ? q.x : (hd == 1 ? q.y : (hd == 2 ? q.z : q.w))) * izh;
        float4 hv = *(const float4*)(h + (size_t)s * F + 4 * lane);
        acc.x = fmaf(al, hv.x, acc.x); acc.y = fmaf(al, hv.y, acc.y);
        acc.z = fmaf(al, hv.z, acc.z); acc.w = fmaf(al, hv.w, acc.w);
    }
    *(float4*)(xout + (size_t)node * F + 4 * lane) = acc;
}

// ---------------- group-attention mixer -------------------------------------
__global__ __launch_bounds__(256) void mix_kernel(
    const float* __restrict__ xout, const float* __restrict__ xg,
    const int* __restrict__ nbr, const int* __restrict__ nlist,
    const int* __restrict__ gstart, float* __restrict__ outf)
{
    __shared__ float srows[17 * 128];
    __shared__ int rowid[17];
    int g = blockIdx.x;
    int tid = threadIdx.x;
    if (tid < 17) rowid[tid] = (tid == 0) ? g : nbr[g * 16 + tid - 1];
    __syncthreads();
    for (int i = tid; i < 17 * 128; i += 256)
        srows[i] = xg[(size_t)rowid[i >> 7] * F + (i & 127)];
    __syncthreads();
    int start = gstart[g], end = gstart[g + 1];
    int lane = tid & 31, w = tid >> 5;
    for (int j = start + w; j < end; j += 8) {
        int node = nlist[j];
        float4 x4 = *(const float4*)(xout + (size_t)node * F + 4 * lane);
        float s[17];
#pragma unroll
        for (int k = 0; k < 17; k++) {
            float4 c = *(const float4*)(srows + k * 128 + 4 * lane);
            float dv = x4.x * c.x + x4.y * c.y + x4.z * c.z + x4.w * c.w;
#pragma unroll
            for (int o = 16; o; o >>= 1) dv += __shfl_xor_sync(FULL, dv, o);
            s[k] = dv;
        }
        float mx = s[0];
#pragma unroll
        for (int k = 1; k < 17; k++) mx = fmaxf(mx, s[k]);
        float sum = 0.f;
#pragma unroll
        for (int k = 0; k < 17; k++) { s[k] = __expf(s[k] - mx); sum += s[k]; }
        float inv = 1.f / sum;
        float4 g4 = make_float4(0.f, 0.f, 0.f, 0.f);
#pragma unroll
        for (int k = 0; k < 17; k++) {
            float wk = s[k] * inv;
            float4 c = *(const float4*)(srows + k * 128 + 4 * lane);
            g4.x = fmaf(wk, c.x, g4.x); g4.y = fmaf(wk, c.y, g4.y);
            g4.z = fmaf(wk, c.z, g4.z); g4.w = fmaf(wk, c.w, g4.w);
        }
        float4 o4 = make_float4(0.5f * (x4.x + g4.x), 0.5f * (x4.y + g4.y),
                                0.5f * (x4.z + g4.z), 0.5f * (x4.w + g4.w));
        *(float4*)(outf + (size_t)node * F + 4 * lane) = o4;
    }
}

// ---------------- streams/events (static init, pre-checkpoint) --------------
namespace {
struct SideStream {
    cudaStream_t s1 = nullptr;
    cudaEvent_t evFork = nullptr, evCSR = nullptr, evS1 = nullptr;
    bool ok = false;
    SideStream() {
        ok = (cudaStreamCreateWithFlags(&s1, cudaStreamNonBlocking) == cudaSuccess) &&
             (cudaEventCreateWithFlags(&evFork, cudaEventDisableTiming) == cudaSuccess) &&
             (cudaEventCreateWithFlags(&evCSR, cudaEventDisableTiming) == cudaSuccess) &&
             (cudaEventCreateWithFlags(&evS1, cudaEventDisableTiming) == cudaSuccess);
    }
};
SideStream g_ss;
}

// ---------------- host ------------------------------------------------------
extern "C" void kernel_launch(void* const* d_in, const int* in_sizes, int n_in,
                              void* d_out, int out_size)
{
    const float* x    = (const float*)d_in[0];
    const int*   ei   = (const int*)  d_in[1];
    const float* xg   = (const float*)d_in[2];
    const int*   eig  = (const int*)  d_in[3];
    const int*   gidx = (const int*)  d_in[4];
    const int*   nbr  = (const int*)  d_in[5];
    const float* W1   = (const float*)d_in[6];
    const float* as1  = (const float*)d_in[7];
    const float* ad1  = (const float*)d_in[8];
    const float* b1   = (const float*)d_in[9];
    const float* W2   = (const float*)d_in[10];
    const float* as2  = (const float*)d_in[11];
    const float* ad2  = (const float*)d_in[12];
    const float* b2   = (const float*)d_in[13];

    float* out    = (float*)d_out;
    float* out_xf = out;
    float* out_xg = out_xf + (size_t)N1 * F;
    float* out_a1 = out_xg + (size_t)K1 * F;
    float* out_a2 = out_a1 + (size_t)ET1 * H;

    float *p_h1, *p_as1, *p_ad1, *p_xout, *p_p1;
    float *p_hg, *p_asg, *p_adg, *p_pg;
    int *p_deg_all, *p_rs1, *p_csrc1, *p_ceid1;
    int *p_rsg, *p_csrcg, *p_ceidg, *p_gs, *p_nlist;
    cudaGetSymbolAddress((void**)&p_h1,     g_h1);
    cudaGetSymbolAddress((void**)&p_as1,    g_as1);
    cudaGetSymbolAddress((void**)&p_ad1,    g_ad1);
    cudaGetSymbolAddress((void**)&p_xout,   g_xout);
    cudaGetSymbolAddress((void**)&p_p1,     g_p1);
    cudaGetSymbolAddress((void**)&p_hg,     g_hg);
    cudaGetSymbolAddress((void**)&p_asg,    g_asg);
    cudaGetSymbolAddress((void**)&p_adg,    g_adg);
    cudaGetSymbolAddress((void**)&p_pg,     g_pg);
    cudaGetSymbolAddress((void**)&p_deg_all,g_deg_all);
    cudaGetSymbolAddress((void**)&p_rs1,    g_rs1);
    cudaGetSymbolAddress((void**)&p_csrc1,  g_csrc1);
    cudaGetSymbolAddress((void**)&p_ceid1,  g_ceid1);
    cudaGetSymbolAddress((void**)&p_rsg,    g_rsg);
    cudaGetSymbolAddress((void**)&p_csrcg,  g_csrcg);
    cudaGetSymbolAddress((void**)&p_ceidg,  g_ceidg);
    cudaGetSymbolAddress((void**)&p_gs,     g_gs);
    cudaGetSymbolAddress((void**)&p_nlist,  g_nlist);

    const int* src1 = ei;
    const int* dst1 = ei + E1;
    const int* srcg = eig;
    const int* dstg = eig + EG;

    bool fork = g_ss.ok;
    cudaStream_t s1 = fork ? g_ss.s1 : (cudaStream_t)0;

    if (fork) {
        cudaEventRecord(g_ss.evFork, 0);
        cudaStreamWaitEvent(s1, g_ss.evFork, 0);
    }

    // ---- side branch A: CSR builds ----
    cudaMemsetAsync(p_deg_all, 0, (N1 + 2 * K1) * sizeof(int), s1);
    hist_all_kernel<<<(ET1 + 255) / 256, 256, 0, s1>>>(dst1, dstg, gidx);
    scanA_kernel<<<NB1, 1024, 0, s1>>>();
    scanB_kernel<<<1, 1024, 0, s1>>>();
    scanC_kernel<<<NB1, 1024, 0, s1>>>();
    scatter_all_kernel<<<(ET1 + 255) / 256, 256, 0, s1>>>(src1, dst1, srcg, dstg, gidx);
    if (fork) cudaEventRecord(g_ss.evCSR, s1);

    // ---- side branch B: group-graph pipeline (overlaps main aggr) ----
    gemm_att_kernel<<<(K1 + RPW * 8 - 1) / (RPW * 8), 256, 0, s1>>>(
        xg, W2, as2, ad2, p_hg, p_asg, p_adg, K1);
    gat_aggr_kernel<<<(K1 * 32 + 255) / 256, 256, 0, s1>>>(
        p_csrcg, p_ceidg, p_rsg, p_asg, p_adg, p_hg, b2, p_pg, out_xg, out_a2, K1);
    if (fork) cudaEventRecord(g_ss.evS1, s1);

    // ---- main branch: big GEMM (overlaps side CSR) ----
    gemm_att_kernel<<<(N1 + RPW * 8 - 1) / (RPW * 8), 256>>>(
        x, W1, as1, ad1, p_h1, p_as1, p_ad1, N1);

    if (fork) cudaStreamWaitEvent(0, g_ss.evCSR, 0);

    // ---- main softmax + aggregate ----
    gat_aggr_kernel<<<(N1 * 32 + 255) / 256, 256>>>(
        p_csrc1, p_ceid1, p_rs1, p_as1, p_ad1, p_h1, b1, p_p1, p_xout, out_a1, N1);

    if (fork) cudaStreamWaitEvent(0, g_ss.evS1, 0);

    // ---- group-attention mixer -> x_final ----
    mix_kernel<<<K1, 256>>>(p_xout, out_xg, nbr, p_nlist, p_gs, out_xf);
}